// round 1
// baseline (speedup 1.0000x reference)
#include <cuda_runtime.h>

#define N_NODES 20000
#define N_EDGES 320000
#define F_NODE 64
#define F_EDGE 16
#define HID 300
#define N_GRAPHS 128

// Scratch (device globals; no allocations allowed)
__device__ float g_h0[N_EDGES * HID];   // 384 MB
__device__ float g_hA[N_EDGES * HID];   // 384 MB
__device__ float g_hB[N_EDGES * HID];   // 384 MB
__device__ float g_aA[N_NODES * HID];   // 24 MB
__device__ float g_aB[N_NODES * HID];   // 24 MB
__device__ float g_pooled[N_GRAPHS * HID];

#define MODE_INIT 0
#define MODE_CONV 1
#define MODE_E2N  2

// Tiled fp32 GEMM with fused gather (A built on the fly) and fused scatter epilogue.
// BM=128, BN=64, BK=16, 256 threads, 8x4 microtile per thread.
template<int MODE, int K>
__global__ __launch_bounds__(256)
void gemm_fused_kernel(
    const float* __restrict__ x,          // INIT/E2N: node features
    const float* __restrict__ edge_attr,  // INIT
    const int*   __restrict__ row,        // INIT/CONV: gather index per edge
    const int*   __restrict__ scat_idx,   // INIT/CONV: col per edge; E2N: batch per node
    const float* __restrict__ aIn,        // CONV: node-aggregated msgs; E2N: s
    const float* __restrict__ hIn,        // CONV: previous h (for rev-edge subtract)
    const float* __restrict__ W,          // [K, HID] row-major
    const float* __restrict__ bias,       // [HID]
    const float* __restrict__ h0,         // CONV: skip connection
    float* __restrict__ hOut,             // INIT/CONV: output h
    float* __restrict__ scatterOut,       // aNext (INIT/CONV) or pooled (E2N)
    int M)
{
    __shared__ float As[16][129];   // [k][m], padded
    __shared__ float Bs[16][64];    // [k][n]
    __shared__ int   s_row[128];

    const int tid = threadIdx.x;
    const int bm = blockIdx.x * 128;
    const int bn = blockIdx.y * 64;

    if (MODE != MODE_E2N) {
        if (tid < 128) {
            int m = bm + tid;
            s_row[tid] = (m < M) ? row[m] : 0;
        }
        __syncthreads();
    }

    float acc[8][4];
    #pragma unroll
    for (int i = 0; i < 8; i++)
        #pragma unroll
        for (int j = 0; j < 4; j++) acc[i][j] = 0.f;

    const int tm = tid >> 4;        // 0..15 -> rows tm*8 .. tm*8+7
    const int tn = tid & 15;        // 0..15 -> cols tn*4 .. tn*4+3

    const int la_e0 = tid >> 4;     // A load: e = la_e0 + i*16, k = la_k
    const int la_k  = tid & 15;
    const int lb_n  = tid & 63;     // B load: n = lb_n, k = lb_k + i*4
    const int lb_k  = tid >> 6;

    for (int k0 = 0; k0 < K; k0 += 16) {
        // ---- stage A tile: built on the fly (gather / rev-subtract) ----
        #pragma unroll
        for (int i = 0; i < 8; i++) {
            int e = la_e0 + i * 16;
            int k = k0 + la_k;
            int m = bm + e;
            float v = 0.f;
            if (k < K && m < M) {
                if (MODE == MODE_INIT) {
                    v = (k < F_NODE) ? x[s_row[e] * F_NODE + k]
                                     : edge_attr[m * F_EDGE + (k - F_NODE)];
                } else if (MODE == MODE_CONV) {
                    v = aIn[s_row[e] * HID + k] - hIn[(m ^ 1) * HID + k];
                } else { // E2N: rows are nodes
                    v = (k < F_NODE) ? x[m * F_NODE + k]
                                     : aIn[m * HID + (k - F_NODE)];
                }
            }
            As[la_k][e] = v;
        }
        // ---- stage B tile: W[k][n] ----
        #pragma unroll
        for (int i = 0; i < 4; i++) {
            int k = k0 + lb_k + i * 4;
            int n = bn + lb_n;
            float v = 0.f;
            if (k < K && n < HID) v = W[k * HID + n];
            Bs[lb_k + i * 4][lb_n] = v;
        }
        __syncthreads();

        #pragma unroll
        for (int kk = 0; kk < 16; kk++) {
            float af[8], bf[4];
            #pragma unroll
            for (int i = 0; i < 8; i++) af[i] = As[kk][tm * 8 + i];
            #pragma unroll
            for (int j = 0; j < 4; j++) bf[j] = Bs[kk][tn * 4 + j];
            #pragma unroll
            for (int i = 0; i < 8; i++)
                #pragma unroll
                for (int j = 0; j < 4; j++)
                    acc[i][j] = fmaf(af[i], bf[j], acc[i][j]);
        }
        __syncthreads();
    }

    // ---- epilogue: bias + skip + relu, write h, scatter-add ----
    #pragma unroll
    for (int i = 0; i < 8; i++) {
        int m = bm + tm * 8 + i;
        if (m >= M) continue;
        int sc = scat_idx[m];
        #pragma unroll
        for (int j = 0; j < 4; j++) {
            int n = bn + tn * 4 + j;
            if (n >= HID) continue;
            float v = acc[i][j] + bias[n];
            if (MODE == MODE_CONV) v += h0[m * HID + n];
            v = fmaxf(v, 0.f);
            if (MODE != MODE_E2N) hOut[m * HID + n] = v;
            atomicAdd(&scatterOut[sc * HID + n], v);
        }
    }
}

__global__ void zero_kernel(float* __restrict__ p, int n) {
    int i = blockIdx.x * blockDim.x + threadIdx.x;
    if (i < n) p[i] = 0.f;
}

// pooled [G, HID] @ W_ffn [HID, 1] + b -> out [G]
__global__ void ffn_kernel(const float* __restrict__ pooled,
                           const float* __restrict__ W,
                           const float* __restrict__ b,
                           float* __restrict__ out) {
    int g = blockIdx.x;
    int lane = threadIdx.x;
    float s = 0.f;
    for (int k = lane; k < HID; k += 32)
        s += pooled[g * HID + k] * W[k];
    #pragma unroll
    for (int o = 16; o > 0; o >>= 1)
        s += __shfl_xor_sync(0xFFFFFFFFu, s, o);
    if (lane == 0) out[g] = s + b[0];
}

extern "C" void kernel_launch(void* const* d_in, const int* in_sizes, int n_in,
                              void* d_out, int out_size) {
    const float* x         = (const float*)d_in[0];
    const float* edge_attr = (const float*)d_in[1];
    const int*   edge_idx  = (const int*)  d_in[2];
    const int*   batch     = (const int*)  d_in[3];
    const float* W_init    = (const float*)d_in[4];
    const float* b_init    = (const float*)d_in[5];
    const float* W_convs   = (const float*)d_in[6];
    const float* b_convs   = (const float*)d_in[7];
    const float* W_e2n     = (const float*)d_in[8];
    const float* b_e2n     = (const float*)d_in[9];
    const float* W_ffn     = (const float*)d_in[10];
    const float* b_ffn     = (const float*)d_in[11];
    float* out = (float*)d_out;

    const int* row = edge_idx;
    const int* col = edge_idx + N_EDGES;

    float *h0, *hA, *hB, *aA, *aB, *pooled;
    cudaGetSymbolAddress((void**)&h0, g_h0);
    cudaGetSymbolAddress((void**)&hA, g_hA);
    cudaGetSymbolAddress((void**)&hB, g_hB);
    cudaGetSymbolAddress((void**)&aA, g_aA);
    cudaGetSymbolAddress((void**)&aB, g_aB);
    cudaGetSymbolAddress((void**)&pooled, g_pooled);

    const int NA = N_NODES * HID;
    dim3 gE((N_EDGES + 127) / 128, (HID + 63) / 64);   // 2500 x 5
    dim3 gN((N_NODES + 127) / 128, (HID + 63) / 64);   // 157 x 5

    // h0 = relu(cat(x[row], edge_attr) @ W_init + b); scatter h0 -> aA
    zero_kernel<<<(NA + 255) / 256, 256>>>(aA, NA);
    gemm_fused_kernel<MODE_INIT, F_NODE + F_EDGE><<<gE, 256>>>(
        x, edge_attr, row, col, nullptr, nullptr, W_init, b_init,
        nullptr, h0, aA, N_EDGES);

    // conv0: reads aA, h=h0; writes hA; scatter -> aB
    zero_kernel<<<(NA + 255) / 256, 256>>>(aB, NA);
    gemm_fused_kernel<MODE_CONV, HID><<<gE, 256>>>(
        nullptr, nullptr, row, col, aA, h0, W_convs + 0 * HID * HID,
        b_convs + 0 * HID, h0, hA, aB, N_EDGES);

    // conv1: reads aB, hA; writes hB; scatter -> aA
    zero_kernel<<<(NA + 255) / 256, 256>>>(aA, NA);
    gemm_fused_kernel<MODE_CONV, HID><<<gE, 256>>>(
        nullptr, nullptr, row, col, aB, hA, W_convs + 1 * HID * HID,
        b_convs + 1 * HID, h0, hB, aA, N_EDGES);

    // conv2: reads aA, hB; writes hA (unused); scatter -> aB (= s)
    zero_kernel<<<(NA + 255) / 256, 256>>>(aB, NA);
    gemm_fused_kernel<MODE_CONV, HID><<<gE, 256>>>(
        nullptr, nullptr, row, col, aA, hB, W_convs + 2 * HID * HID,
        b_convs + 2 * HID, h0, hA, aB, N_EDGES);

    // e2n: hn = relu(cat(x, s) @ W_e2n + b); scatter by batch -> pooled
    zero_kernel<<<(N_GRAPHS * HID + 255) / 256, 256>>>(pooled, N_GRAPHS * HID);
    gemm_fused_kernel<MODE_E2N, F_NODE + HID><<<gN, 256>>>(
        x, nullptr, nullptr, batch, aB, nullptr, W_e2n, b_e2n,
        nullptr, nullptr, pooled, N_NODES);

    // out = pooled @ W_ffn + b
    ffn_kernel<<<N_GRAPHS, 32>>>(pooled, W_ffn, b_ffn, out);
}

// round 4
// speedup vs baseline: 3.8471x; 3.8471x over previous
#include <cuda_runtime.h>
#include <cuda_bf16.h>
#include <cstdint>

#define N_NODES 20000
#define N_EDGES 320000
#define F_NODE 64
#define F_EDGE 16
#define HID 300
#define N_GRAPHS 128

#define MODE_INIT 0
#define MODE_CONV 1
#define MODE_E2N  2

#define N_PAD 320
#define KCHUNK 32
#define TOTAL_WCHUNKS 45                      // 3 init + 10*3 conv + 12 e2n
#define WCHUNK_ELEMS (N_PAD * KCHUNK)         // 10240
#define WCHUNK_BYTES (WCHUNK_ELEMS * 2)       // 20480

// SMEM layout (bytes): s_row [0,256), A tiles [256,16640) = 4 x 4KB
// (buf0 hi, buf0 lo, buf1 hi, buf1 lo), B tiles [16640,98560) = 4 x 20KB.
#define SMEM_SROW 0
#define SMEM_A_OFF 256
#define SMEM_B_OFF 16640
#define SMEM_TOTAL 98560

// ---------------- scratch (device globals; no allocations allowed) -------------
__device__ float g_h0[(size_t)N_EDGES * HID];
__device__ float g_hA[(size_t)N_EDGES * HID];
__device__ float g_hB[(size_t)N_EDGES * HID];
__device__ float g_aA[N_NODES * HID];
__device__ float g_aB[N_NODES * HID];
__device__ float g_pooled[N_GRAPHS * HID];
__device__ __align__(16) unsigned char g_Whi[(size_t)TOTAL_WCHUNKS * WCHUNK_BYTES];
__device__ __align__(16) unsigned char g_Wlo[(size_t)TOTAL_WCHUNKS * WCHUNK_BYTES];

// ---------------- helpers ----------------
__device__ __forceinline__ uint32_t smem_to_u32(const void* p) {
    uint32_t a;
    asm("{ .reg .u64 t; cvta.to.shared.u64 t, %1; cvt.u32.u64 %0, t; }" : "=r"(a) : "l"(p));
    return a;
}

#define LDSM_X4(r, addr) \
    asm volatile("ldmatrix.sync.aligned.m8n8.x4.shared.b16 {%0,%1,%2,%3}, [%4];" \
                 : "=r"((r)[0]), "=r"((r)[1]), "=r"((r)[2]), "=r"((r)[3]) : "r"(addr))

#define MMA_BF16(d, a, b) \
    asm volatile("mma.sync.aligned.m16n8k16.row.col.f32.bf16.bf16.f32 " \
                 "{%0,%1,%2,%3}, {%4,%5,%6,%7}, {%8,%9}, {%0,%1,%2,%3};" \
                 : "+f"((d)[0]), "+f"((d)[1]), "+f"((d)[2]), "+f"((d)[3]) \
                 : "r"((a)[0]), "r"((a)[1]), "r"((a)[2]), "r"((a)[3]), \
                   "r"((b)[0]), "r"((b)[1]))

#define CP_ASYNC16(dst, src) \
    asm volatile("cp.async.cg.shared.global [%0], [%1], 16;" \
                 :: "r"(dst), "l"(src) : "memory")
#define CP_COMMIT() asm volatile("cp.async.commit_group;" ::: "memory")
#define CP_WAIT0()  asm volatile("cp.async.wait_group 0;" ::: "memory")

__device__ __forceinline__ void split2(float a, float b, uint32_t& hi, uint32_t& lo) {
    __nv_bfloat16 ah = __float2bfloat16(a);
    __nv_bfloat16 bh = __float2bfloat16(b);
    __nv_bfloat16 al = __float2bfloat16(a - __bfloat162float(ah));
    __nv_bfloat16 bl = __float2bfloat16(b - __bfloat162float(bh));
    hi = (uint32_t)__bfloat16_as_ushort(ah) | ((uint32_t)__bfloat16_as_ushort(bh) << 16);
    lo = (uint32_t)__bfloat16_as_ushort(al) | ((uint32_t)__bfloat16_as_ushort(bl) << 16);
}

// 64B-row XOR swizzle: 16B group g at row r lands at group g ^ ((r>>1)&3)
__device__ __host__ __forceinline__ uint32_t swzoff(uint32_t row, uint32_t grp) {
    return row * 64u + ((grp ^ ((row >> 1) & 3u)) << 4);
}

// ---------------- weight prep: split + transpose + N-permute + swizzle ---------
// Logical column n_log -> physical row n_phys so that a thread's HMMA d-fragment
// columns across an n8-tile pair are 4 contiguous logical columns.
__global__ void prep_weights(const float* __restrict__ Wi,
                             const float* __restrict__ Wc,
                             const float* __restrict__ We) {
    int idx = blockIdx.x * blockDim.x + threadIdx.x;
    if (idx >= TOTAL_WCHUNKS * WCHUNK_ELEMS) return;
    int chunk = idx / WCHUNK_ELEMS;
    int rem   = idx % WCHUNK_ELEMS;
    int n_log = rem >> 5;       // 0..319
    int k     = rem & 31;       // 0..31
    const float* W; int K; int c;
    if (chunk < 3)       { W = Wi;               K = F_NODE + F_EDGE; c = chunk; }
    else if (chunk < 13) { W = Wc + 0 * HID*HID; K = HID;             c = chunk - 3; }
    else if (chunk < 23) { W = Wc + 1 * HID*HID; K = HID;             c = chunk - 13; }
    else if (chunk < 33) { W = Wc + 2 * HID*HID; K = HID;             c = chunk - 23; }
    else                 { W = We;               K = F_NODE + HID;    c = chunk - 33; }
    int ka = c * KCHUNK + k;
    float v = (ka < K && n_log < HID) ? W[(size_t)ka * HID + n_log] : 0.f;
    __nv_bfloat16 hi = __float2bfloat16(v);
    __nv_bfloat16 lo = __float2bfloat16(v - __bfloat162float(hi));
    // permutation: n_log = p*16 + q*4 + r  ->  n_phys = p*16 + (r>>1)*8 + q*2 + (r&1)
    int p = n_log >> 4, q = (n_log >> 2) & 3, r = n_log & 3;
    int n_phys = p * 16 + (r >> 1) * 8 + q * 2 + (r & 1);
    uint32_t off = swzoff((uint32_t)n_phys, (uint32_t)(k >> 3)) + (uint32_t)((k & 7) * 2);
    *(__nv_bfloat16*)(g_Whi + (size_t)chunk * WCHUNK_BYTES + off) = hi;
    *(__nv_bfloat16*)(g_Wlo + (size_t)chunk * WCHUNK_BYTES + off) = lo;
}

// ---------------- fused HMMA kernel ----------------
// BM=64 rows x BN=320 (full N), K chunks of 32, double-buffered, 256 threads.
// Warp grid 2(M) x 4(N); warp tile 32x80; mma.sync m16n8k16 bf16, hi/lo split.
struct Pref { float4 a0, a1, b0, b1; };

template<int MODE, int K, int C, int WBASE, bool WRITE_H>
__global__ __launch_bounds__(256, 1)
void fused_mma(const float* __restrict__ x,
               const float* __restrict__ edge_attr,
               const int*   __restrict__ rowIdx,
               const int*   __restrict__ scat_idx,
               const float* __restrict__ aIn,
               const float* __restrict__ hIn,
               const float* __restrict__ bias,
               const float* __restrict__ h0,
               float* __restrict__ hOut,
               float* __restrict__ scatterOut,
               int M) {
    extern __shared__ char smem[];
    const uint32_t smem_u = smem_to_u32(smem);
    const int tid = threadIdx.x;
    const int bm = blockIdx.x * 64;
    int* s_row = (int*)(smem + SMEM_SROW);

    if (MODE != MODE_E2N) {
        if (tid < 64) s_row[tid] = rowIdx[bm + tid];
    }
    __syncthreads();

    const int lane = tid & 31;
    const int wid  = tid >> 5;
    const int wm   = wid >> 2;   // 0..1
    const int wn   = wid & 3;    // 0..3

    // staging coords: each thread handles row r, 8 k-elems starting at q*8
    const int r = tid >> 2;
    const int q = tid & 3;
    const int m_st = bm + r;

    float acc[80];
    #pragma unroll
    for (int i = 0; i < 80; i++) acc[i] = 0.f;

    auto loadA = [&](int c) -> Pref {
        Pref pf;
        pf.a0 = pf.a1 = pf.b0 = pf.b1 = make_float4(0.f, 0.f, 0.f, 0.f);
        const int ka = c * KCHUNK + q * 8;
        if (MODE == MODE_CONV) {
            const float* ap = aIn + (size_t)s_row[r] * HID + ka;
            const float* hp = hIn + (size_t)(bm + (r ^ 1)) * HID + ka;
            if (ka + 4 <= K) { pf.a0 = *(const float4*)ap; pf.b0 = *(const float4*)hp; }
            if (ka + 8 <= K) { pf.a1 = *(const float4*)(ap + 4); pf.b1 = *(const float4*)(hp + 4); }
        } else if (MODE == MODE_INIT) {
            if (ka + 4 <= F_NODE)
                pf.a0 = *(const float4*)(x + (size_t)s_row[r] * F_NODE + ka);
            else if (ka >= F_NODE && ka + 4 <= F_NODE + F_EDGE)
                pf.a0 = *(const float4*)(edge_attr + (size_t)m_st * F_EDGE + (ka - F_NODE));
            int kb = ka + 4;
            if (kb + 4 <= F_NODE)
                pf.a1 = *(const float4*)(x + (size_t)s_row[r] * F_NODE + kb);
            else if (kb >= F_NODE && kb + 4 <= F_NODE + F_EDGE)
                pf.a1 = *(const float4*)(edge_attr + (size_t)m_st * F_EDGE + (kb - F_NODE));
        } else { // E2N
            if (m_st < M) {
                if (ka + 4 <= F_NODE)
                    pf.a0 = *(const float4*)(x + (size_t)m_st * F_NODE + ka);
                else if (ka >= F_NODE && ka + 4 <= K)
                    pf.a0 = *(const float4*)(aIn + (size_t)m_st * HID + (ka - F_NODE));
                int kb = ka + 4;
                if (kb + 4 <= F_NODE)
                    pf.a1 = *(const float4*)(x + (size_t)m_st * F_NODE + kb);
                else if (kb >= F_NODE && kb + 4 <= K)
                    pf.a1 = *(const float4*)(aIn + (size_t)m_st * HID + (kb - F_NODE));
            }
        }
        return pf;
    };

    auto storeA = [&](int buf, const Pref& pf) {
        float v[8];
        if (MODE == MODE_CONV) {
            v[0] = pf.a0.x - pf.b0.x; v[1] = pf.a0.y - pf.b0.y;
            v[2] = pf.a0.z - pf.b0.z; v[3] = pf.a0.w - pf.b0.w;
            v[4] = pf.a1.x - pf.b1.x; v[5] = pf.a1.y - pf.b1.y;
            v[6] = pf.a1.z - pf.b1.z; v[7] = pf.a1.w - pf.b1.w;
        } else {
            v[0] = pf.a0.x; v[1] = pf.a0.y; v[2] = pf.a0.z; v[3] = pf.a0.w;
            v[4] = pf.a1.x; v[5] = pf.a1.y; v[6] = pf.a1.z; v[7] = pf.a1.w;
        }
        uint4 hi, lo;
        split2(v[0], v[1], hi.x, lo.x);
        split2(v[2], v[3], hi.y, lo.y);
        split2(v[4], v[5], hi.z, lo.z);
        split2(v[6], v[7], hi.w, lo.w);
        const uint32_t off = swzoff((uint32_t)r, (uint32_t)q);
        *(uint4*)(smem + SMEM_A_OFF + (buf * 2 + 0) * 4096 + off) = hi;
        *(uint4*)(smem + SMEM_A_OFF + (buf * 2 + 1) * 4096 + off) = lo;
    };

    auto issueB = [&](int c, int buf) {
        #pragma unroll
        for (int comp = 0; comp < 2; comp++) {
            const unsigned char* src = (comp ? g_Wlo : g_Whi)
                + (size_t)(WBASE + c) * WCHUNK_BYTES + tid * 16;
            uint32_t dst = smem_u + SMEM_B_OFF + (buf * 2 + comp) * WCHUNK_BYTES + tid * 16;
            #pragma unroll
            for (int i = 0; i < 5; i++)
                CP_ASYNC16(dst + i * 4096, src + i * 4096);
        }
    };

    auto mmaChunk = [&](int buf) {
        const uint32_t Ahi = smem_u + SMEM_A_OFF + (buf * 2 + 0) * 4096;
        const uint32_t Alo = smem_u + SMEM_A_OFF + (buf * 2 + 1) * 4096;
        const uint32_t Bhi = smem_u + SMEM_B_OFF + (buf * 2 + 0) * WCHUNK_BYTES;
        const uint32_t Blo = smem_u + SMEM_B_OFF + (buf * 2 + 1) * WCHUNK_BYTES;
        #pragma unroll
        for (int ks = 0; ks < 2; ks++) {
            uint32_t ah[2][4], al[2][4];
            const uint32_t agrp = (uint32_t)(ks * 2 + (lane >> 4));
            #pragma unroll
            for (int mt = 0; mt < 2; mt++) {
                const uint32_t row = (uint32_t)(wm * 32 + mt * 16 + (lane & 15));
                const uint32_t off = swzoff(row, agrp);
                LDSM_X4(ah[mt], Ahi + off);
                LDSM_X4(al[mt], Alo + off);
            }
            #pragma unroll
            for (int pp = 0; pp < 5; pp++) {
                const uint32_t nrow = (uint32_t)(wn * 80 + pp * 16 + ((lane >> 4) << 3) + (lane & 7));
                const uint32_t bgrp = (uint32_t)(ks * 2 + ((lane >> 3) & 1));
                const uint32_t off = swzoff(nrow, bgrp);
                uint32_t bh[4], bl[4];
                LDSM_X4(bh, Bhi + off);
                LDSM_X4(bl, Blo + off);
                #pragma unroll
                for (int mt = 0; mt < 2; mt++) {
                    #pragma unroll
                    for (int nt = 0; nt < 2; nt++) {
                        float* d = &acc[(mt * 10 + pp * 2 + nt) * 4];
                        MMA_BF16(d, ah[mt], &bh[nt * 2]);
                        MMA_BF16(d, ah[mt], &bl[nt * 2]);
                        MMA_BF16(d, al[mt], &bh[nt * 2]);
                    }
                }
            }
        }
    };

    // prologue: stage chunk 0
    {
        Pref p0 = loadA(0);
        issueB(0, 0);
        storeA(0, p0);
        CP_COMMIT();
        CP_WAIT0();
    }
    __syncthreads();

    for (int c = 0; c < C; c++) {
        const int buf = c & 1;
        Pref pn;
        const bool more = (c + 1 < C);
        if (more) {
            pn = loadA(c + 1);
            issueB(c + 1, buf ^ 1);
            CP_COMMIT();
        }
        mmaChunk(buf);
        if (more) {
            storeA(buf ^ 1, pn);
            CP_WAIT0();
            __syncthreads();
        }
    }

    // ---- epilogue: bias + skip + relu, h write, vectorized scatter-add ----
    #pragma unroll
    for (int mt = 0; mt < 2; mt++) {
        #pragma unroll
        for (int rh = 0; rh < 2; rh++) {
            const int m = bm + wm * 32 + mt * 16 + (lane >> 2) + rh * 8;
            if (m >= M) continue;
            const int sc = scat_idx[m];
            const float* h0r = h0 + (size_t)m * HID;
            float* hor = hOut + (size_t)m * HID;
            float* scr = scatterOut + (size_t)sc * HID;
            #pragma unroll
            for (int pp = 0; pp < 5; pp++) {
                const int n = wn * 80 + pp * 16 + (lane & 3) * 4;
                if (n >= HID) continue;
                const float* d0 = &acc[(mt * 10 + pp * 2 + 0) * 4];
                const float* d1 = &acc[(mt * 10 + pp * 2 + 1) * 4];
                float4 v;
                v.x = d0[rh * 2 + 0]; v.y = d0[rh * 2 + 1];
                v.z = d1[rh * 2 + 0]; v.w = d1[rh * 2 + 1];
                const float4 bb = __ldg((const float4*)(bias + n));
                v.x += bb.x; v.y += bb.y; v.z += bb.z; v.w += bb.w;
                if (MODE == MODE_CONV) {
                    const float4 s = *(const float4*)(h0r + n);
                    v.x += s.x; v.y += s.y; v.z += s.z; v.w += s.w;
                }
                v.x = fmaxf(v.x, 0.f); v.y = fmaxf(v.y, 0.f);
                v.z = fmaxf(v.z, 0.f); v.w = fmaxf(v.w, 0.f);
                if (WRITE_H) *(float4*)(hor + n) = v;
                asm volatile("red.global.add.v4.f32 [%0], {%1, %2, %3, %4};"
                             :: "l"(scr + n), "f"(v.x), "f"(v.y), "f"(v.z), "f"(v.w)
                             : "memory");
            }
        }
    }
}

__global__ void zero_kernel(float4* __restrict__ p, int n4) {
    int i = blockIdx.x * blockDim.x + threadIdx.x;
    if (i < n4) p[i] = make_float4(0.f, 0.f, 0.f, 0.f);
}

__global__ void ffn_kernel(const float* __restrict__ pooled,
                           const float* __restrict__ W,
                           const float* __restrict__ b,
                           float* __restrict__ out) {
    int g = blockIdx.x;
    int lane = threadIdx.x;
    float s = 0.f;
    for (int k = lane; k < HID; k += 32)
        s += pooled[g * HID + k] * W[k];
    #pragma unroll
    for (int o = 16; o > 0; o >>= 1)
        s += __shfl_xor_sync(0xFFFFFFFFu, s, o);
    if (lane == 0) out[g] = s + b[0];
}

extern "C" void kernel_launch(void* const* d_in, const int* in_sizes, int n_in,
                              void* d_out, int out_size) {
    const float* x         = (const float*)d_in[0];
    const float* edge_attr = (const float*)d_in[1];
    const int*   edge_idx  = (const int*)  d_in[2];
    const int*   batch     = (const int*)  d_in[3];
    const float* W_init    = (const float*)d_in[4];
    const float* b_init    = (const float*)d_in[5];
    const float* W_convs   = (const float*)d_in[6];
    const float* b_convs   = (const float*)d_in[7];
    const float* W_e2n     = (const float*)d_in[8];
    const float* b_e2n     = (const float*)d_in[9];
    const float* W_ffn     = (const float*)d_in[10];
    const float* b_ffn     = (const float*)d_in[11];
    float* out = (float*)d_out;

    const int* row = edge_idx;
    const int* col = edge_idx + N_EDGES;

    float *h0, *hA, *hB, *aA, *aB, *pooled;
    cudaGetSymbolAddress((void**)&h0, g_h0);
    cudaGetSymbolAddress((void**)&hA, g_hA);
    cudaGetSymbolAddress((void**)&hB, g_hB);
    cudaGetSymbolAddress((void**)&aA, g_aA);
    cudaGetSymbolAddress((void**)&aB, g_aB);
    cudaGetSymbolAddress((void**)&pooled, g_pooled);

    cudaFuncSetAttribute(fused_mma<MODE_INIT, F_NODE + F_EDGE, 3, 0, true>,
                         cudaFuncAttributeMaxDynamicSharedMemorySize, SMEM_TOTAL);
    cudaFuncSetAttribute(fused_mma<MODE_CONV, HID, 10, 3, true>,
                         cudaFuncAttributeMaxDynamicSharedMemorySize, SMEM_TOTAL);
    cudaFuncSetAttribute(fused_mma<MODE_CONV, HID, 10, 13, true>,
                         cudaFuncAttributeMaxDynamicSharedMemorySize, SMEM_TOTAL);
    cudaFuncSetAttribute(fused_mma<MODE_CONV, HID, 10, 23, false>,
                         cudaFuncAttributeMaxDynamicSharedMemorySize, SMEM_TOTAL);
    cudaFuncSetAttribute(fused_mma<MODE_E2N, F_NODE + HID, 12, 33, false>,
                         cudaFuncAttributeMaxDynamicSharedMemorySize, SMEM_TOTAL);

    const int NA = N_NODES * HID;
    const int gE = N_EDGES / 64;               // 5000
    const int gN = (N_NODES + 63) / 64;        // 313

    // weight preprocessing (split + transpose + permute + swizzle)
    prep_weights<<<(TOTAL_WCHUNKS * WCHUNK_ELEMS + 255) / 256, 256>>>(W_init, W_convs, W_e2n);

    // init: h0 = relu(cat(x[row], edge_attr) @ W_init + b); scatter -> aA
    zero_kernel<<<(NA / 4 + 255) / 256, 256>>>((float4*)aA, NA / 4);
    fused_mma<MODE_INIT, F_NODE + F_EDGE, 3, 0, true><<<gE, 256, SMEM_TOTAL>>>(
        x, edge_attr, row, col, nullptr, nullptr, b_init, h0, h0, aA, N_EDGES);

    // conv0: A = aA[row] - rev(h0); h = relu(A@W0 + b0 + h0); scatter -> aB
    zero_kernel<<<(NA / 4 + 255) / 256, 256>>>((float4*)aB, NA / 4);
    fused_mma<MODE_CONV, HID, 10, 3, true><<<gE, 256, SMEM_TOTAL>>>(
        nullptr, nullptr, row, col, aA, h0, b_convs + 0 * HID, h0, hA, aB, N_EDGES);

    // conv1
    zero_kernel<<<(NA / 4 + 255) / 256, 256>>>((float4*)aA, NA / 4);
    fused_mma<MODE_CONV, HID, 10, 13, true><<<gE, 256, SMEM_TOTAL>>>(
        nullptr, nullptr, row, col, aB, hA, b_convs + 1 * HID, h0, hB, aA, N_EDGES);

    // conv2: scatter only -> aB (= s); h not written
    zero_kernel<<<(NA / 4 + 255) / 256, 256>>>((float4*)aB, NA / 4);
    fused_mma<MODE_CONV, HID, 10, 23, false><<<gE, 256, SMEM_TOTAL>>>(
        nullptr, nullptr, row, col, aA, hB, b_convs + 2 * HID, h0, hA, aB, N_EDGES);

    // e2n: hn = relu(cat(x, s) @ W_e2n + b); scatter by batch -> pooled
    zero_kernel<<<(N_GRAPHS * HID / 4 + 255) / 256, 256>>>((float4*)pooled, N_GRAPHS * HID / 4);
    fused_mma<MODE_E2N, F_NODE + HID, 12, 33, false><<<gN, 256, SMEM_TOTAL>>>(
        x, nullptr, nullptr, batch, aB, nullptr, b_e2n, h0, hA, pooled, N_NODES);

    // out = pooled @ W_ffn + b
    ffn_kernel<<<N_GRAPHS, 32>>>(pooled, W_ffn, b_ffn, out);
}

// round 6
// speedup vs baseline: 4.5634x; 1.1862x over previous
#include <cuda_runtime.h>
#include <cuda_fp16.h>
#include <cstdint>

#define N_NODES 20000
#define N_EDGES 320000
#define F_NODE 64
#define F_EDGE 16
#define HID 300
#define N_GRAPHS 128

#define MODE_INIT 0
#define MODE_CONV 1
#define MODE_E2N  2

#define N_PAD 320
#define KCHUNK 32
#define TOTAL_WCHUNKS 45                      // 3 init + 10*3 conv + 12 e2n
#define WCHUNK_ELEMS (N_PAD * KCHUNK)         // 10240
#define WCHUNK_BYTES (WCHUNK_ELEMS * 2)       // 20480

// SMEM layout (bytes): s_row [0,256), A tiles [256,8448) = 2 x 4KB (fp16, single),
// B tiles [8448,90368) = 4 x 20KB (buf0 hi, buf0 lo, buf1 hi, buf1 lo).
#define SMEM_SROW 0
#define SMEM_A_OFF 256
#define SMEM_B_OFF 8448
#define SMEM_TOTAL 90368

// ---------------- scratch (device globals; no allocations allowed) -------------
__device__ float g_h0[(size_t)N_EDGES * HID];
__device__ float g_hA[(size_t)N_EDGES * HID];
__device__ float g_hB[(size_t)N_EDGES * HID];
__device__ float g_aA[N_NODES * HID];
__device__ float g_aB[N_NODES * HID];
__device__ float g_pooled[N_GRAPHS * HID];
__device__ __align__(16) unsigned char g_Whi[(size_t)TOTAL_WCHUNKS * WCHUNK_BYTES];
__device__ __align__(16) unsigned char g_Wlo[(size_t)TOTAL_WCHUNKS * WCHUNK_BYTES];

// ---------------- helpers ----------------
__device__ __forceinline__ uint32_t smem_to_u32(const void* p) {
    uint32_t a;
    asm("{ .reg .u64 t; cvta.to.shared.u64 t, %1; cvt.u32.u64 %0, t; }" : "=r"(a) : "l"(p));
    return a;
}

#define LDSM_X4(r, addr) \
    asm volatile("ldmatrix.sync.aligned.m8n8.x4.shared.b16 {%0,%1,%2,%3}, [%4];" \
                 : "=r"((r)[0]), "=r"((r)[1]), "=r"((r)[2]), "=r"((r)[3]) : "r"(addr))

#define MMA_F16(d, a, b) \
    asm volatile("mma.sync.aligned.m16n8k16.row.col.f32.f16.f16.f32 " \
                 "{%0,%1,%2,%3}, {%4,%5,%6,%7}, {%8,%9}, {%0,%1,%2,%3};" \
                 : "+f"((d)[0]), "+f"((d)[1]), "+f"((d)[2]), "+f"((d)[3]) \
                 : "r"((a)[0]), "r"((a)[1]), "r"((a)[2]), "r"((a)[3]), \
                   "r"((b)[0]), "r"((b)[1]))

#define CP_ASYNC16(dst, src) \
    asm volatile("cp.async.cg.shared.global [%0], [%1], 16;" \
                 :: "r"(dst), "l"(src) : "memory")
#define CP_COMMIT() asm volatile("cp.async.commit_group;" ::: "memory")
#define CP_WAIT0()  asm volatile("cp.async.wait_group 0;" ::: "memory")

__device__ __forceinline__ uint32_t pack_h2(float a, float b) {
    __half2 h = __floats2half2_rn(a, b);
    return *(uint32_t*)&h;
}

// 64B-row XOR swizzle: 16B group g at row r lands at group g ^ ((r>>1)&3)
__device__ __host__ __forceinline__ uint32_t swzoff(uint32_t row, uint32_t grp) {
    return row * 64u + ((grp ^ ((row >> 1) & 3u)) << 4);
}

// ---------------- weight prep: fp16 split + transpose + N-permute + swizzle ----
__global__ void prep_weights(const float* __restrict__ Wi,
                             const float* __restrict__ Wc,
                             const float* __restrict__ We) {
    int idx = blockIdx.x * blockDim.x + threadIdx.x;
    if (idx >= TOTAL_WCHUNKS * WCHUNK_ELEMS) return;
    int chunk = idx / WCHUNK_ELEMS;
    int rem   = idx % WCHUNK_ELEMS;
    int n_log = rem >> 5;       // 0..319
    int k     = rem & 31;       // 0..31
    const float* W; int K; int c;
    if (chunk < 3)       { W = Wi;               K = F_NODE + F_EDGE; c = chunk; }
    else if (chunk < 13) { W = Wc + 0 * HID*HID; K = HID;             c = chunk - 3; }
    else if (chunk < 23) { W = Wc + 1 * HID*HID; K = HID;             c = chunk - 13; }
    else if (chunk < 33) { W = Wc + 2 * HID*HID; K = HID;             c = chunk - 23; }
    else                 { W = We;               K = F_NODE + HID;    c = chunk - 33; }
    int ka = c * KCHUNK + k;
    float v = (ka < K && n_log < HID) ? W[(size_t)ka * HID + n_log] : 0.f;
    __half hi = __float2half_rn(v);
    __half lo = __float2half_rn(v - __half2float(hi));
    // permutation: n_log = p*16 + q*4 + r  ->  n_phys = p*16 + (r>>1)*8 + q*2 + (r&1)
    int p = n_log >> 4, q = (n_log >> 2) & 3, r = n_log & 3;
    int n_phys = p * 16 + (r >> 1) * 8 + q * 2 + (r & 1);
    uint32_t off = swzoff((uint32_t)n_phys, (uint32_t)(k >> 3)) + (uint32_t)((k & 7) * 2);
    *(__half*)(g_Whi + (size_t)chunk * WCHUNK_BYTES + off) = hi;
    *(__half*)(g_Wlo + (size_t)chunk * WCHUNK_BYTES + off) = lo;
}

// ---------------- fused HMMA kernel ----------------
// BM=64 rows x BN=320 (full N), K chunks of 32, double-buffered, 256 threads.
// Warp grid 2(M) x 4(N); warp tile 32x80; mma.sync m16n8k16 f16.
// A single fp16; B pre-split fp16 hi/lo -> 2 MMAs per subtile, reordered so
// consecutive MMAs target different accumulators (RAW distance 4).
struct Pref { float4 a0, a1, b0, b1; };

template<int MODE, int K, int C, int WBASE, bool WRITE_H>
__global__ __launch_bounds__(256, 1)
void fused_mma(const float* __restrict__ x,
               const float* __restrict__ edge_attr,
               const int*   __restrict__ rowIdx,
               const int*   __restrict__ scat_idx,
               const float* __restrict__ aIn,
               const float* __restrict__ hIn,
               const float* __restrict__ bias,
               const float* __restrict__ h0,
               float* __restrict__ hOut,
               float* __restrict__ scatterOut,
               int M) {
    extern __shared__ char smem[];
    const uint32_t smem_u = smem_to_u32(smem);
    const int tid = threadIdx.x;
    const int bm = blockIdx.x * 64;
    int* s_row = (int*)(smem + SMEM_SROW);

    if (MODE != MODE_E2N) {
        if (tid < 64) s_row[tid] = rowIdx[bm + tid];
    }
    __syncthreads();

    const int lane = tid & 31;
    const int wid  = tid >> 5;
    const int wm   = wid >> 2;   // 0..1
    const int wn   = wid & 3;    // 0..3

    // staging coords: each thread handles row r, 8 k-elems starting at q*8
    const int r = tid >> 2;
    const int q = tid & 3;
    const int m_st = bm + r;

    float acc[80];
    #pragma unroll
    for (int i = 0; i < 80; i++) acc[i] = 0.f;

    auto loadA = [&](int c) -> Pref {
        Pref pf;
        pf.a0 = pf.a1 = pf.b0 = pf.b1 = make_float4(0.f, 0.f, 0.f, 0.f);
        const int ka = c * KCHUNK + q * 8;
        if (MODE == MODE_CONV) {
            const float* ap = aIn + (size_t)s_row[r] * HID + ka;
            const float* hp = hIn + (size_t)(bm + (r ^ 1)) * HID + ka;
            if (ka + 4 <= K) { pf.a0 = *(const float4*)ap; pf.b0 = *(const float4*)hp; }
            if (ka + 8 <= K) { pf.a1 = *(const float4*)(ap + 4); pf.b1 = *(const float4*)(hp + 4); }
        } else if (MODE == MODE_INIT) {
            if (ka + 4 <= F_NODE)
                pf.a0 = *(const float4*)(x + (size_t)s_row[r] * F_NODE + ka);
            else if (ka >= F_NODE && ka + 4 <= F_NODE + F_EDGE)
                pf.a0 = *(const float4*)(edge_attr + (size_t)m_st * F_EDGE + (ka - F_NODE));
            int kb = ka + 4;
            if (kb + 4 <= F_NODE)
                pf.a1 = *(const float4*)(x + (size_t)s_row[r] * F_NODE + kb);
            else if (kb >= F_NODE && kb + 4 <= F_NODE + F_EDGE)
                pf.a1 = *(const float4*)(edge_attr + (size_t)m_st * F_EDGE + (kb - F_NODE));
        } else { // E2N
            if (m_st < M) {
                if (ka + 4 <= F_NODE)
                    pf.a0 = *(const float4*)(x + (size_t)m_st * F_NODE + ka);
                else if (ka >= F_NODE && ka + 4 <= K)
                    pf.a0 = *(const float4*)(aIn + (size_t)m_st * HID + (ka - F_NODE));
                int kb = ka + 4;
                if (kb + 4 <= F_NODE)
                    pf.a1 = *(const float4*)(x + (size_t)m_st * F_NODE + kb);
                else if (kb >= F_NODE && kb + 4 <= K)
                    pf.a1 = *(const float4*)(aIn + (size_t)m_st * HID + (kb - F_NODE));
            }
        }
        return pf;
    };

    auto storeA = [&](int buf, const Pref& pf) {
        float v[8];
        if (MODE == MODE_CONV) {
            v[0] = pf.a0.x - pf.b0.x; v[1] = pf.a0.y - pf.b0.y;
            v[2] = pf.a0.z - pf.b0.z; v[3] = pf.a0.w - pf.b0.w;
            v[4] = pf.a1.x - pf.b1.x; v[5] = pf.a1.y - pf.b1.y;
            v[6] = pf.a1.z - pf.b1.z; v[7] = pf.a1.w - pf.b1.w;
        } else {
            v[0] = pf.a0.x; v[1] = pf.a0.y; v[2] = pf.a0.z; v[3] = pf.a0.w;
            v[4] = pf.a1.x; v[5] = pf.a1.y; v[6] = pf.a1.z; v[7] = pf.a1.w;
        }
        uint4 h;
        h.x = pack_h2(v[0], v[1]);
        h.y = pack_h2(v[2], v[3]);
        h.z = pack_h2(v[4], v[5]);
        h.w = pack_h2(v[6], v[7]);
        *(uint4*)(smem + SMEM_A_OFF + buf * 4096 + swzoff((uint32_t)r, (uint32_t)q)) = h;
    };

    auto issueB = [&](int c, int buf) {
        #pragma unroll
        for (int comp = 0; comp < 2; comp++) {
            const unsigned char* src = (comp ? g_Wlo : g_Whi)
                + (size_t)(WBASE + c) * WCHUNK_BYTES + tid * 16;
            uint32_t dst = smem_u + SMEM_B_OFF + (buf * 2 + comp) * WCHUNK_BYTES + tid * 16;
            #pragma unroll
            for (int i = 0; i < 5; i++)
                CP_ASYNC16(dst + i * 4096, src + i * 4096);
        }
    };

    auto mmaChunk = [&](int buf) {
        const uint32_t At  = smem_u + SMEM_A_OFF + buf * 4096;
        const uint32_t Bhi = smem_u + SMEM_B_OFF + (buf * 2 + 0) * WCHUNK_BYTES;
        const uint32_t Blo = smem_u + SMEM_B_OFF + (buf * 2 + 1) * WCHUNK_BYTES;
        #pragma unroll
        for (int ks = 0; ks < 2; ks++) {
            uint32_t af[2][4];
            const uint32_t agrp = (uint32_t)(ks * 2 + (lane >> 4));
            #pragma unroll
            for (int mt = 0; mt < 2; mt++) {
                const uint32_t row = (uint32_t)(wm * 32 + mt * 16 + (lane & 15));
                LDSM_X4(af[mt], At + swzoff(row, agrp));
            }
            #pragma unroll
            for (int pp = 0; pp < 5; pp++) {
                const uint32_t nrow = (uint32_t)(wn * 80 + pp * 16 + ((lane >> 4) << 3) + (lane & 7));
                const uint32_t bgrp = (uint32_t)(ks * 2 + ((lane >> 3) & 1));
                const uint32_t off = swzoff(nrow, bgrp);
                uint32_t bh[4], bl[4];
                LDSM_X4(bh, Bhi + off);
                LDSM_X4(bl, Blo + off);
                // split-major: all 4 accumulators on hi, then all 4 on lo
                #pragma unroll
                for (int mt = 0; mt < 2; mt++)
                    #pragma unroll
                    for (int nt = 0; nt < 2; nt++)
                        MMA_F16(&acc[(mt * 10 + pp * 2 + nt) * 4], af[mt], &bh[nt * 2]);
                #pragma unroll
                for (int mt = 0; mt < 2; mt++)
                    #pragma unroll
                    for (int nt = 0; nt < 2; nt++)
                        MMA_F16(&acc[(mt * 10 + pp * 2 + nt) * 4], af[mt], &bl[nt * 2]);
            }
        }
    };

    // prologue: stage chunk 0
    {
        Pref p0 = loadA(0);
        issueB(0, 0);
        storeA(0, p0);
        CP_COMMIT();
        CP_WAIT0();
    }
    __syncthreads();

    for (int c = 0; c < C; c++) {
        const int buf = c & 1;
        Pref pn;
        const bool more = (c + 1 < C);
        if (more) {
            pn = loadA(c + 1);
            issueB(c + 1, buf ^ 1);
            CP_COMMIT();
        }
        mmaChunk(buf);
        if (more) {
            storeA(buf ^ 1, pn);
            CP_WAIT0();
            __syncthreads();
        }
    }

    // ---- epilogue: bias + skip + relu, h write, vectorized scatter-add ----
    #pragma unroll
    for (int mt = 0; mt < 2; mt++) {
        #pragma unroll
        for (int rh = 0; rh < 2; rh++) {
            const int m = bm + wm * 32 + mt * 16 + (lane >> 2) + rh * 8;
            if (m >= M) continue;
            const int sc = scat_idx[m];
            const float* h0r = h0 + (size_t)m * HID;
            float* hor = hOut + (size_t)m * HID;
            float* scr = scatterOut + (size_t)sc * HID;
            #pragma unroll
            for (int pp = 0; pp < 5; pp++) {
                const int n = wn * 80 + pp * 16 + (lane & 3) * 4;
                if (n >= HID) continue;
                const float* d0 = &acc[(mt * 10 + pp * 2 + 0) * 4];
                const float* d1 = &acc[(mt * 10 + pp * 2 + 1) * 4];
                float4 v;
                v.x = d0[rh * 2 + 0]; v.y = d0[rh * 2 + 1];
                v.z = d1[rh * 2 + 0]; v.w = d1[rh * 2 + 1];
                const float4 bb = __ldg((const float4*)(bias + n));
                v.x += bb.x; v.y += bb.y; v.z += bb.z; v.w += bb.w;
                if (MODE == MODE_CONV) {
                    const float4 s = *(const float4*)(h0r + n);
                    v.x += s.x; v.y += s.y; v.z += s.z; v.w += s.w;
                }
                v.x = fmaxf(v.x, 0.f); v.y = fmaxf(v.y, 0.f);
                v.z = fmaxf(v.z, 0.f); v.w = fmaxf(v.w, 0.f);
                if (WRITE_H) *(float4*)(hor + n) = v;
                asm volatile("red.global.add.v4.f32 [%0], {%1, %2, %3, %4};"
                             :: "l"(scr + n), "f"(v.x), "f"(v.y), "f"(v.z), "f"(v.w)
                             : "memory");
            }
        }
    }
}

__global__ void zero_kernel(float4* __restrict__ p, int n4) {
    int i = blockIdx.x * blockDim.x + threadIdx.x;
    if (i < n4) p[i] = make_float4(0.f, 0.f, 0.f, 0.f);
}

__global__ void ffn_kernel(const float* __restrict__ pooled,
                           const float* __restrict__ W,
                           const float* __restrict__ b,
                           float* __restrict__ out) {
    int g = blockIdx.x;
    int lane = threadIdx.x;
    float s = 0.f;
    for (int k = lane; k < HID; k += 32)
        s += pooled[g * HID + k] * W[k];
    #pragma unroll
    for (int o = 16; o > 0; o >>= 1)
        s += __shfl_xor_sync(0xFFFFFFFFu, s, o);
    if (lane == 0) out[g] = s + b[0];
}

extern "C" void kernel_launch(void* const* d_in, const int* in_sizes, int n_in,
                              void* d_out, int out_size) {
    const float* x         = (const float*)d_in[0];
    const float* edge_attr = (const float*)d_in[1];
    const int*   edge_idx  = (const int*)  d_in[2];
    const int*   batch     = (const int*)  d_in[3];
    const float* W_init    = (const float*)d_in[4];
    const float* b_init    = (const float*)d_in[5];
    const float* W_convs   = (const float*)d_in[6];
    const float* b_convs   = (const float*)d_in[7];
    const float* W_e2n     = (const float*)d_in[8];
    const float* b_e2n     = (const float*)d_in[9];
    const float* W_ffn     = (const float*)d_in[10];
    const float* b_ffn     = (const float*)d_in[11];
    float* out = (float*)d_out;

    const int* row = edge_idx;
    const int* col = edge_idx + N_EDGES;

    float *h0, *hA, *hB, *aA, *aB, *pooled;
    cudaGetSymbolAddress((void**)&h0, g_h0);
    cudaGetSymbolAddress((void**)&hA, g_hA);
    cudaGetSymbolAddress((void**)&hB, g_hB);
    cudaGetSymbolAddress((void**)&aA, g_aA);
    cudaGetSymbolAddress((void**)&aB, g_aB);
    cudaGetSymbolAddress((void**)&pooled, g_pooled);

    cudaFuncSetAttribute(fused_mma<MODE_INIT, F_NODE + F_EDGE, 3, 0, true>,
                         cudaFuncAttributeMaxDynamicSharedMemorySize, SMEM_TOTAL);
    cudaFuncSetAttribute(fused_mma<MODE_CONV, HID, 10, 3, true>,
                         cudaFuncAttributeMaxDynamicSharedMemorySize, SMEM_TOTAL);
    cudaFuncSetAttribute(fused_mma<MODE_CONV, HID, 10, 13, true>,
                         cudaFuncAttributeMaxDynamicSharedMemorySize, SMEM_TOTAL);
    cudaFuncSetAttribute(fused_mma<MODE_CONV, HID, 10, 23, false>,
                         cudaFuncAttributeMaxDynamicSharedMemorySize, SMEM_TOTAL);
    cudaFuncSetAttribute(fused_mma<MODE_E2N, F_NODE + HID, 12, 33, false>,
                         cudaFuncAttributeMaxDynamicSharedMemorySize, SMEM_TOTAL);

    const int NA = N_NODES * HID;
    const int gE = N_EDGES / 64;               // 5000
    const int gN = (N_NODES + 63) / 64;        // 313

    // weight preprocessing (fp16 split + transpose + permute + swizzle)
    prep_weights<<<(TOTAL_WCHUNKS * WCHUNK_ELEMS + 255) / 256, 256>>>(W_init, W_convs, W_e2n);

    // init: h0 = relu(cat(x[row], edge_attr) @ W_init + b); scatter -> aA
    zero_kernel<<<(NA / 4 + 255) / 256, 256>>>((float4*)aA, NA / 4);
    fused_mma<MODE_INIT, F_NODE + F_EDGE, 3, 0, true><<<gE, 256, SMEM_TOTAL>>>(
        x, edge_attr, row, col, nullptr, nullptr, b_init, h0, h0, aA, N_EDGES);

    // conv0: A = aA[row] - rev(h0); h = relu(A@W0 + b0 + h0); scatter -> aB
    zero_kernel<<<(NA / 4 + 255) / 256, 256>>>((float4*)aB, NA / 4);
    fused_mma<MODE_CONV, HID, 10, 3, true><<<gE, 256, SMEM_TOTAL>>>(
        nullptr, nullptr, row, col, aA, h0, b_convs + 0 * HID, h0, hA, aB, N_EDGES);

    // conv1
    zero_kernel<<<(NA / 4 + 255) / 256, 256>>>((float4*)aA, NA / 4);
    fused_mma<MODE_CONV, HID, 10, 13, true><<<gE, 256, SMEM_TOTAL>>>(
        nullptr, nullptr, row, col, aB, hA, b_convs + 1 * HID, h0, hB, aA, N_EDGES);

    // conv2: scatter only -> aB (= s); h not written
    zero_kernel<<<(NA / 4 + 255) / 256, 256>>>((float4*)aB, NA / 4);
    fused_mma<MODE_CONV, HID, 10, 23, false><<<gE, 256, SMEM_TOTAL>>>(
        nullptr, nullptr, row, col, aA, hB, b_convs + 2 * HID, h0, hA, aB, N_EDGES);

    // e2n: hn = relu(cat(x, s) @ W_e2n + b); scatter by batch -> pooled
    zero_kernel<<<(N_GRAPHS * HID / 4 + 255) / 256, 256>>>((float4*)pooled, N_GRAPHS * HID / 4);
    fused_mma<MODE_E2N, F_NODE + HID, 12, 33, false><<<gN, 256, SMEM_TOTAL>>>(
        x, nullptr, nullptr, batch, aB, nullptr, b_e2n, h0, hA, pooled, N_NODES);

    // out = pooled @ W_ffn + b
    ffn_kernel<<<N_GRAPHS, 32>>>(pooled, W_ffn, b_ffn, out);
}

// round 7
// speedup vs baseline: 6.0458x; 1.3249x over previous
#include <cuda_runtime.h>
#include <cuda_fp16.h>
#include <cstdint>

#define N_NODES 20000
#define N_EDGES 320000
#define F_NODE 64
#define F_EDGE 16
#define HID 300
#define N_GRAPHS 128

#define MODE_INIT 0
#define MODE_CONV 1
#define MODE_E2N  2

#define N_PAD 320
#define KCHUNK 32
#define TOTAL_WCHUNKS 45                      // 3 init + 10*3 conv + 12 e2n
#define WCHUNK_ELEMS (N_PAD * KCHUNK)         // 10240
#define WCHUNK_BYTES (WCHUNK_ELEMS * 2)       // 20480

// SMEM layout (bytes): s_row [0,256), A tiles [256,8448) = 2 x 4KB (fp16),
// B tiles [8448,49408) = 2 x 20KB (fp16 single).
#define SMEM_SROW 0
#define SMEM_A_OFF 256
#define SMEM_B_OFF 8448
#define SMEM_TOTAL 49408

// ---------------- scratch (device globals; no allocations allowed) -------------
__device__ __half g_h0[(size_t)N_EDGES * HID];   // 192 MB
__device__ __half g_hA[(size_t)N_EDGES * HID];   // 192 MB
__device__ __half g_hB[(size_t)N_EDGES * HID];   // 192 MB
__device__ float  g_aA[N_NODES * HID];           // 24 MB (L2-resident)
__device__ float  g_aB[N_NODES * HID];           // 24 MB
__device__ float  g_pooled[N_GRAPHS * HID];
__device__ __align__(16) unsigned char g_W[(size_t)TOTAL_WCHUNKS * WCHUNK_BYTES];

// ---------------- helpers ----------------
__device__ __forceinline__ uint32_t smem_to_u32(const void* p) {
    uint32_t a;
    asm("{ .reg .u64 t; cvta.to.shared.u64 t, %1; cvt.u32.u64 %0, t; }" : "=r"(a) : "l"(p));
    return a;
}

#define LDSM_X4(r, addr) \
    asm volatile("ldmatrix.sync.aligned.m8n8.x4.shared.b16 {%0,%1,%2,%3}, [%4];" \
                 : "=r"((r)[0]), "=r"((r)[1]), "=r"((r)[2]), "=r"((r)[3]) : "r"(addr))

#define MMA_F16(d, a, b) \
    asm volatile("mma.sync.aligned.m16n8k16.row.col.f32.f16.f16.f32 " \
                 "{%0,%1,%2,%3}, {%4,%5,%6,%7}, {%8,%9}, {%0,%1,%2,%3};" \
                 : "+f"((d)[0]), "+f"((d)[1]), "+f"((d)[2]), "+f"((d)[3]) \
                 : "r"((a)[0]), "r"((a)[1]), "r"((a)[2]), "r"((a)[3]), \
                   "r"((b)[0]), "r"((b)[1]))

#define CP_ASYNC16(dst, src) \
    asm volatile("cp.async.cg.shared.global [%0], [%1], 16;" \
                 :: "r"(dst), "l"(src) : "memory")
#define CP_COMMIT() asm volatile("cp.async.commit_group;" ::: "memory")
#define CP_WAIT0()  asm volatile("cp.async.wait_group 0;" ::: "memory")

__device__ __forceinline__ uint32_t pack_h2(float a, float b) {
    __half2 h = __floats2half2_rn(a, b);
    return *(uint32_t*)&h;
}
__device__ __forceinline__ float2 unpack_h2(uint32_t u) {
    __half2 h = *(__half2*)&u;
    return __half22float2(h);
}

// 64B-row XOR swizzle: 16B group g at row r lands at group g ^ ((r>>1)&3)
__device__ __host__ __forceinline__ uint32_t swzoff(uint32_t row, uint32_t grp) {
    return row * 64u + ((grp ^ ((row >> 1) & 3u)) << 4);
}

// ---------------- weight prep: fp16 + transpose + N-permute + swizzle ----------
__global__ void prep_weights(const float* __restrict__ Wi,
                             const float* __restrict__ Wc,
                             const float* __restrict__ We) {
    int idx = blockIdx.x * blockDim.x + threadIdx.x;
    if (idx >= TOTAL_WCHUNKS * WCHUNK_ELEMS) return;
    int chunk = idx / WCHUNK_ELEMS;
    int rem   = idx % WCHUNK_ELEMS;
    int n_log = rem >> 5;       // 0..319
    int k     = rem & 31;       // 0..31
    const float* W; int K; int c;
    if (chunk < 3)       { W = Wi;               K = F_NODE + F_EDGE; c = chunk; }
    else if (chunk < 13) { W = Wc + 0 * HID*HID; K = HID;             c = chunk - 3; }
    else if (chunk < 23) { W = Wc + 1 * HID*HID; K = HID;             c = chunk - 13; }
    else if (chunk < 33) { W = Wc + 2 * HID*HID; K = HID;             c = chunk - 23; }
    else                 { W = We;               K = F_NODE + HID;    c = chunk - 33; }
    int ka = c * KCHUNK + k;
    float v = (ka < K && n_log < HID) ? W[(size_t)ka * HID + n_log] : 0.f;
    // permutation: n_log = p*16 + q*4 + r  ->  n_phys = p*16 + (r>>1)*8 + q*2 + (r&1)
    int p = n_log >> 4, q = (n_log >> 2) & 3, r = n_log & 3;
    int n_phys = p * 16 + (r >> 1) * 8 + q * 2 + (r & 1);
    uint32_t off = swzoff((uint32_t)n_phys, (uint32_t)(k >> 3)) + (uint32_t)((k & 7) * 2);
    *(__half*)(g_W + (size_t)chunk * WCHUNK_BYTES + off) = __float2half_rn(v);
}

// ---------------- fused HMMA kernel ----------------
// BM=64 rows x BN=320 (full N), K chunks of 32, double-buffered, 256 threads.
// Warp grid 2(M) x 4(N); warp tile 32x80; mma.sync m16n8k16 f16 (no split).
// h arrays stored fp16; scatter accumulators fp32.
struct Pref { float4 a0, a1; uint2 h0v, h1v; };

template<int MODE, int K, int C, int WBASE, bool WRITE_H>
__global__ __launch_bounds__(256, 1)
void fused_mma(const float* __restrict__ x,
               const float* __restrict__ edge_attr,
               const int*   __restrict__ rowIdx,
               const int*   __restrict__ scat_idx,
               const float* __restrict__ aIn,
               const __half* __restrict__ hIn,
               const float* __restrict__ bias,
               const __half* __restrict__ h0,
               __half* __restrict__ hOut,
               float* __restrict__ scatterOut,
               int M) {
    extern __shared__ char smem[];
    const uint32_t smem_u = smem_to_u32(smem);
    const int tid = threadIdx.x;
    const int bm = blockIdx.x * 64;
    int* s_row = (int*)(smem + SMEM_SROW);

    if (MODE != MODE_E2N) {
        if (tid < 64) s_row[tid] = rowIdx[bm + tid];
    }
    __syncthreads();

    const int lane = tid & 31;
    const int wid  = tid >> 5;
    const int wm   = wid >> 2;   // 0..1
    const int wn   = wid & 3;    // 0..3

    // staging coords: each thread handles row r, 8 k-elems starting at q*8
    const int r = tid >> 2;
    const int q = tid & 3;
    const int m_st = bm + r;

    float acc[80];
    #pragma unroll
    for (int i = 0; i < 80; i++) acc[i] = 0.f;

    auto loadA = [&](int c) -> Pref {
        Pref pf;
        pf.a0 = pf.a1 = make_float4(0.f, 0.f, 0.f, 0.f);
        pf.h0v = pf.h1v = make_uint2(0u, 0u);
        const int ka = c * KCHUNK + q * 8;
        if (MODE == MODE_CONV) {
            const float* ap = aIn + (size_t)s_row[r] * HID + ka;
            const __half* hp = hIn + (size_t)(bm + (r ^ 1)) * HID + ka;
            if (ka + 4 <= K) { pf.a0 = *(const float4*)ap; pf.h0v = *(const uint2*)hp; }
            if (ka + 8 <= K) { pf.a1 = *(const float4*)(ap + 4); pf.h1v = *(const uint2*)(hp + 4); }
        } else if (MODE == MODE_INIT) {
            if (ka + 4 <= F_NODE)
                pf.a0 = *(const float4*)(x + (size_t)s_row[r] * F_NODE + ka);
            else if (ka >= F_NODE && ka + 4 <= F_NODE + F_EDGE)
                pf.a0 = *(const float4*)(edge_attr + (size_t)m_st * F_EDGE + (ka - F_NODE));
            int kb = ka + 4;
            if (kb + 4 <= F_NODE)
                pf.a1 = *(const float4*)(x + (size_t)s_row[r] * F_NODE + kb);
            else if (kb >= F_NODE && kb + 4 <= F_NODE + F_EDGE)
                pf.a1 = *(const float4*)(edge_attr + (size_t)m_st * F_EDGE + (kb - F_NODE));
        } else { // E2N
            if (m_st < M) {
                if (ka + 4 <= F_NODE)
                    pf.a0 = *(const float4*)(x + (size_t)m_st * F_NODE + ka);
                else if (ka >= F_NODE && ka + 4 <= K)
                    pf.a0 = *(const float4*)(aIn + (size_t)m_st * HID + (ka - F_NODE));
                int kb = ka + 4;
                if (kb + 4 <= F_NODE)
                    pf.a1 = *(const float4*)(x + (size_t)m_st * F_NODE + kb);
                else if (kb + 4 <= K)
                    pf.a1 = *(const float4*)(aIn + (size_t)m_st * HID + (kb - F_NODE));
            }
        }
        return pf;
    };

    auto storeA = [&](int buf, const Pref& pf) {
        uint4 h;
        if (MODE == MODE_CONV) {
            float2 h0a = unpack_h2(pf.h0v.x), h0b = unpack_h2(pf.h0v.y);
            float2 h1a = unpack_h2(pf.h1v.x), h1b = unpack_h2(pf.h1v.y);
            h.x = pack_h2(pf.a0.x - h0a.x, pf.a0.y - h0a.y);
            h.y = pack_h2(pf.a0.z - h0b.x, pf.a0.w - h0b.y);
            h.z = pack_h2(pf.a1.x - h1a.x, pf.a1.y - h1a.y);
            h.w = pack_h2(pf.a1.z - h1b.x, pf.a1.w - h1b.y);
        } else {
            h.x = pack_h2(pf.a0.x, pf.a0.y);
            h.y = pack_h2(pf.a0.z, pf.a0.w);
            h.z = pack_h2(pf.a1.x, pf.a1.y);
            h.w = pack_h2(pf.a1.z, pf.a1.w);
        }
        *(uint4*)(smem + SMEM_A_OFF + buf * 4096 + swzoff((uint32_t)r, (uint32_t)q)) = h;
    };

    auto issueB = [&](int c, int buf) {
        const unsigned char* src = g_W + (size_t)(WBASE + c) * WCHUNK_BYTES + tid * 16;
        uint32_t dst = smem_u + SMEM_B_OFF + buf * WCHUNK_BYTES + tid * 16;
        #pragma unroll
        for (int i = 0; i < 5; i++)
            CP_ASYNC16(dst + i * 4096, src + i * 4096);
    };

    auto mmaChunk = [&](int buf) {
        const uint32_t At = smem_u + SMEM_A_OFF + buf * 4096;
        const uint32_t Bt = smem_u + SMEM_B_OFF + buf * WCHUNK_BYTES;
        #pragma unroll
        for (int ks = 0; ks < 2; ks++) {
            uint32_t af[2][4];
            const uint32_t agrp = (uint32_t)(ks * 2 + (lane >> 4));
            #pragma unroll
            for (int mt = 0; mt < 2; mt++) {
                const uint32_t row = (uint32_t)(wm * 32 + mt * 16 + (lane & 15));
                LDSM_X4(af[mt], At + swzoff(row, agrp));
            }
            #pragma unroll
            for (int pp = 0; pp < 5; pp++) {
                const uint32_t nrow = (uint32_t)(wn * 80 + pp * 16 + ((lane >> 4) << 3) + (lane & 7));
                const uint32_t bgrp = (uint32_t)(ks * 2 + ((lane >> 3) & 1));
                uint32_t bf[4];
                LDSM_X4(bf, Bt + swzoff(nrow, bgrp));
                #pragma unroll
                for (int mt = 0; mt < 2; mt++)
                    #pragma unroll
                    for (int nt = 0; nt < 2; nt++)
                        MMA_F16(&acc[(mt * 10 + pp * 2 + nt) * 4], af[mt], &bf[nt * 2]);
            }
        }
    };

    // prologue: stage chunk 0
    {
        Pref p0 = loadA(0);
        issueB(0, 0);
        storeA(0, p0);
        CP_COMMIT();
        CP_WAIT0();
    }
    __syncthreads();

    for (int c = 0; c < C; c++) {
        const int buf = c & 1;
        Pref pn;
        const bool more = (c + 1 < C);
        if (more) {
            pn = loadA(c + 1);
            issueB(c + 1, buf ^ 1);
            CP_COMMIT();
        }
        mmaChunk(buf);
        if (more) {
            storeA(buf ^ 1, pn);
            CP_WAIT0();
            __syncthreads();
        }
    }

    // ---- epilogue: bias + skip + relu, fp16 h write, fp32 scatter-add ----
    #pragma unroll
    for (int mt = 0; mt < 2; mt++) {
        #pragma unroll
        for (int rh = 0; rh < 2; rh++) {
            const int m = bm + wm * 32 + mt * 16 + (lane >> 2) + rh * 8;
            if (m >= M) continue;
            const int sc = scat_idx[m];
            const __half* h0r = h0 + (size_t)m * HID;
            __half* hor = hOut + (size_t)m * HID;
            float* scr = scatterOut + (size_t)sc * HID;
            #pragma unroll
            for (int pp = 0; pp < 5; pp++) {
                const int n = wn * 80 + pp * 16 + (lane & 3) * 4;
                if (n >= HID) continue;
                const float* d0 = &acc[(mt * 10 + pp * 2 + 0) * 4];
                const float* d1 = &acc[(mt * 10 + pp * 2 + 1) * 4];
                float4 v;
                v.x = d0[rh * 2 + 0]; v.y = d0[rh * 2 + 1];
                v.z = d1[rh * 2 + 0]; v.w = d1[rh * 2 + 1];
                const float4 bb = __ldg((const float4*)(bias + n));
                v.x += bb.x; v.y += bb.y; v.z += bb.z; v.w += bb.w;
                if (MODE == MODE_CONV) {
                    const uint2 sr = *(const uint2*)(h0r + n);
                    float2 s0 = unpack_h2(sr.x), s1 = unpack_h2(sr.y);
                    v.x += s0.x; v.y += s0.y; v.z += s1.x; v.w += s1.y;
                }
                v.x = fmaxf(v.x, 0.f); v.y = fmaxf(v.y, 0.f);
                v.z = fmaxf(v.z, 0.f); v.w = fmaxf(v.w, 0.f);
                if (WRITE_H) {
                    uint2 hw;
                    hw.x = pack_h2(v.x, v.y);
                    hw.y = pack_h2(v.z, v.w);
                    *(uint2*)(hor + n) = hw;
                }
                asm volatile("red.global.add.v4.f32 [%0], {%1, %2, %3, %4};"
                             :: "l"(scr + n), "f"(v.x), "f"(v.y), "f"(v.z), "f"(v.w)
                             : "memory");
            }
        }
    }
}

__global__ void zero_kernel(float4* __restrict__ p, int n4) {
    int i = blockIdx.x * blockDim.x + threadIdx.x;
    if (i < n4) p[i] = make_float4(0.f, 0.f, 0.f, 0.f);
}

__global__ void ffn_kernel(const float* __restrict__ pooled,
                           const float* __restrict__ W,
                           const float* __restrict__ b,
                           float* __restrict__ out) {
    int g = blockIdx.x;
    int lane = threadIdx.x;
    float s = 0.f;
    for (int k = lane; k < HID; k += 32)
        s += pooled[g * HID + k] * W[k];
    #pragma unroll
    for (int o = 16; o > 0; o >>= 1)
        s += __shfl_xor_sync(0xFFFFFFFFu, s, o);
    if (lane == 0) out[g] = s + b[0];
}

extern "C" void kernel_launch(void* const* d_in, const int* in_sizes, int n_in,
                              void* d_out, int out_size) {
    const float* x         = (const float*)d_in[0];
    const float* edge_attr = (const float*)d_in[1];
    const int*   edge_idx  = (const int*)  d_in[2];
    const int*   batch     = (const int*)  d_in[3];
    const float* W_init    = (const float*)d_in[4];
    const float* b_init    = (const float*)d_in[5];
    const float* W_convs   = (const float*)d_in[6];
    const float* b_convs   = (const float*)d_in[7];
    const float* W_e2n     = (const float*)d_in[8];
    const float* b_e2n     = (const float*)d_in[9];
    const float* W_ffn     = (const float*)d_in[10];
    const float* b_ffn     = (const float*)d_in[11];
    float* out = (float*)d_out;

    const int* row = edge_idx;
    const int* col = edge_idx + N_EDGES;

    __half *h0, *hA, *hB;
    float *aA, *aB, *pooled;
    cudaGetSymbolAddress((void**)&h0, g_h0);
    cudaGetSymbolAddress((void**)&hA, g_hA);
    cudaGetSymbolAddress((void**)&hB, g_hB);
    cudaGetSymbolAddress((void**)&aA, g_aA);
    cudaGetSymbolAddress((void**)&aB, g_aB);
    cudaGetSymbolAddress((void**)&pooled, g_pooled);

    cudaFuncSetAttribute(fused_mma<MODE_INIT, F_NODE + F_EDGE, 3, 0, true>,
                         cudaFuncAttributeMaxDynamicSharedMemorySize, SMEM_TOTAL);
    cudaFuncSetAttribute(fused_mma<MODE_CONV, HID, 10, 3, true>,
                         cudaFuncAttributeMaxDynamicSharedMemorySize, SMEM_TOTAL);
    cudaFuncSetAttribute(fused_mma<MODE_CONV, HID, 10, 13, true>,
                         cudaFuncAttributeMaxDynamicSharedMemorySize, SMEM_TOTAL);
    cudaFuncSetAttribute(fused_mma<MODE_CONV, HID, 10, 23, false>,
                         cudaFuncAttributeMaxDynamicSharedMemorySize, SMEM_TOTAL);
    cudaFuncSetAttribute(fused_mma<MODE_E2N, F_NODE + HID, 12, 33, false>,
                         cudaFuncAttributeMaxDynamicSharedMemorySize, SMEM_TOTAL);

    const int NA = N_NODES * HID;
    const int gE = N_EDGES / 64;               // 5000
    const int gN = (N_NODES + 63) / 64;        // 313

    // weight preprocessing (fp16 + transpose + permute + swizzle)
    prep_weights<<<(TOTAL_WCHUNKS * WCHUNK_ELEMS + 255) / 256, 256>>>(W_init, W_convs, W_e2n);

    // init: h0 = relu(cat(x[row], edge_attr) @ W_init + b); scatter -> aA
    zero_kernel<<<(NA / 4 + 255) / 256, 256>>>((float4*)aA, NA / 4);
    fused_mma<MODE_INIT, F_NODE + F_EDGE, 3, 0, true><<<gE, 256, SMEM_TOTAL>>>(
        x, edge_attr, row, col, nullptr, nullptr, b_init, h0, h0, aA, N_EDGES);

    // conv0: A = aA[row] - rev(h0); h = relu(A@W0 + b0 + h0); scatter -> aB
    zero_kernel<<<(NA / 4 + 255) / 256, 256>>>((float4*)aB, NA / 4);
    fused_mma<MODE_CONV, HID, 10, 3, true><<<gE, 256, SMEM_TOTAL>>>(
        nullptr, nullptr, row, col, aA, h0, b_convs + 0 * HID, h0, hA, aB, N_EDGES);

    // conv1
    zero_kernel<<<(NA / 4 + 255) / 256, 256>>>((float4*)aA, NA / 4);
    fused_mma<MODE_CONV, HID, 10, 13, true><<<gE, 256, SMEM_TOTAL>>>(
        nullptr, nullptr, row, col, aB, hA, b_convs + 1 * HID, h0, hB, aA, N_EDGES);

    // conv2: scatter only -> aB (= s); h not written
    zero_kernel<<<(NA / 4 + 255) / 256, 256>>>((float4*)aB, NA / 4);
    fused_mma<MODE_CONV, HID, 10, 23, false><<<gE, 256, SMEM_TOTAL>>>(
        nullptr, nullptr, row, col, aA, hB, b_convs + 2 * HID, h0, hA, aB, N_EDGES);

    // e2n: hn = relu(cat(x, s) @ W_e2n + b); scatter by batch -> pooled
    zero_kernel<<<(N_GRAPHS * HID / 4 + 255) / 256, 256>>>((float4*)pooled, N_GRAPHS * HID / 4);
    fused_mma<MODE_E2N, F_NODE + HID, 12, 33, false><<<gN, 256, SMEM_TOTAL>>>(
        x, nullptr, nullptr, batch, aB, nullptr, b_e2n, h0, hA, pooled, N_NODES);

    // out = pooled @ W_ffn + b
    ffn_kernel<<<N_GRAPHS, 32>>>(pooled, W_ffn, b_ffn, out);
}

// round 10
// speedup vs baseline: 6.0588x; 1.0021x over previous
#include <cuda_runtime.h>
#include <cuda_fp16.h>
#include <cstdint>

#define N_NODES 20000
#define N_EDGES 320000
#define F_NODE 64
#define F_EDGE 16
#define HID 300
#define N_GRAPHS 128

#define MODE_INIT 0
#define MODE_CONV 1
#define MODE_E2N  2

#define N_PAD 320
#define KCHUNK 32
#define TOTAL_WCHUNKS 45                      // 3 init + 10*3 conv + 12 e2n
#define WCHUNK_ELEMS (N_PAD * KCHUNK)         // 10240
#define WCHUNK_BYTES (WCHUNK_ELEMS * 2)       // 20480

#define NTHREADS 640

// SMEM layout (bytes): s_row [0,256), A tiles [256,8448) = 2 x 4KB (fp16),
// B tiles [8448,49408) = 2 x 20KB (fp16).
#define SMEM_SROW 0
#define SMEM_A_OFF 256
#define SMEM_B_OFF 8448
#define SMEM_TOTAL 49408

// ---------------- scratch (device globals; no allocations allowed) -------------
__device__ __half g_h0[(size_t)N_EDGES * HID];   // 192 MB
__device__ __half g_hA[(size_t)N_EDGES * HID];   // 192 MB
__device__ __half g_hB[(size_t)N_EDGES * HID];   // 192 MB
__device__ float  g_aA[N_NODES * HID];           // 24 MB (L2-resident)
__device__ float  g_aB[N_NODES * HID];           // 24 MB
__device__ float  g_pooled[N_GRAPHS * HID];
__device__ __align__(16) unsigned char g_W[(size_t)TOTAL_WCHUNKS * WCHUNK_BYTES];

// ---------------- helpers ----------------
__device__ __forceinline__ uint32_t smem_to_u32(const void* p) {
    uint32_t a;
    asm("{ .reg .u64 t; cvta.to.shared.u64 t, %1; cvt.u32.u64 %0, t; }" : "=r"(a) : "l"(p));
    return a;
}

#define LDSM_X4(r, addr) \
    asm volatile("ldmatrix.sync.aligned.m8n8.x4.shared.b16 {%0,%1,%2,%3}, [%4];" \
                 : "=r"((r)[0]), "=r"((r)[1]), "=r"((r)[2]), "=r"((r)[3]) : "r"(addr))

#define MMA_F16(d, a, b) \
    asm volatile("mma.sync.aligned.m16n8k16.row.col.f32.f16.f16.f32 " \
                 "{%0,%1,%2,%3}, {%4,%5,%6,%7}, {%8,%9}, {%0,%1,%2,%3};" \
                 : "+f"((d)[0]), "+f"((d)[1]), "+f"((d)[2]), "+f"((d)[3]) \
                 : "r"((a)[0]), "r"((a)[1]), "r"((a)[2]), "r"((a)[3]), \
                   "r"((b)[0]), "r"((b)[1]))

#define CP_ASYNC16(dst, src) \
    asm volatile("cp.async.cg.shared.global [%0], [%1], 16;" \
                 :: "r"(dst), "l"(src) : "memory")
#define CP_COMMIT() asm volatile("cp.async.commit_group;" ::: "memory")
#define CP_WAIT0()  asm volatile("cp.async.wait_group 0;" ::: "memory")

__device__ __forceinline__ uint32_t pack_h2(float a, float b) {
    __half2 h = __floats2half2_rn(a, b);
    return *(uint32_t*)&h;
}
__device__ __forceinline__ float2 unpack_h2(uint32_t u) {
    __half2 h = *(__half2*)&u;
    return __half22float2(h);
}

// 64B-row XOR swizzle: 16B group g at row r lands at group g ^ ((r>>1)&3)
__device__ __host__ __forceinline__ uint32_t swzoff(uint32_t row, uint32_t grp) {
    return row * 64u + ((grp ^ ((row >> 1) & 3u)) << 4);
}

// ---------------- weight prep: fp16 + transpose + N-permute + swizzle ----------
__global__ void prep_weights(const float* __restrict__ Wi,
                             const float* __restrict__ Wc,
                             const float* __restrict__ We) {
    int idx = blockIdx.x * blockDim.x + threadIdx.x;
    if (idx >= TOTAL_WCHUNKS * WCHUNK_ELEMS) return;
    int chunk = idx / WCHUNK_ELEMS;
    int rem   = idx % WCHUNK_ELEMS;
    int n_log = rem >> 5;       // 0..319
    int k     = rem & 31;       // 0..31
    const float* W; int K; int c;
    if (chunk < 3)       { W = Wi;               K = F_NODE + F_EDGE; c = chunk; }
    else if (chunk < 13) { W = Wc + 0 * HID*HID; K = HID;             c = chunk - 3; }
    else if (chunk < 23) { W = Wc + 1 * HID*HID; K = HID;             c = chunk - 13; }
    else if (chunk < 33) { W = Wc + 2 * HID*HID; K = HID;             c = chunk - 23; }
    else                 { W = We;               K = F_NODE + HID;    c = chunk - 33; }
    int ka = c * KCHUNK + k;
    float v = (ka < K && n_log < HID) ? W[(size_t)ka * HID + n_log] : 0.f;
    // permutation: n_log = p*16 + q*4 + r  ->  n_phys = p*16 + (r>>1)*8 + q*2 + (r&1)
    int p = n_log >> 4, q = (n_log >> 2) & 3, r = n_log & 3;
    int n_phys = p * 16 + (r >> 1) * 8 + q * 2 + (r & 1);
    uint32_t off = swzoff((uint32_t)n_phys, (uint32_t)(k >> 3)) + (uint32_t)((k & 7) * 2);
    *(__half*)(g_W + (size_t)chunk * WCHUNK_BYTES + off) = __float2half_rn(v);
}

// ---------------- fused HMMA kernel ----------------
// BM=64 rows x BN=320 (full N), K chunks of 32, double-buffered, 640 threads.
// Warp grid 2(M) x 10(N); warp tile 32x32; mma.sync m16n8k16 f16.
// h arrays stored fp16; scatter accumulators fp32.
struct Pref { float4 a0; uint2 h0v; };

template<int MODE, int K, int C, int WBASE, bool WRITE_H>
__global__ __launch_bounds__(NTHREADS, 1)
void fused_mma(const float* __restrict__ x,
               const float* __restrict__ edge_attr,
               const int*   __restrict__ rowIdx,
               const int*   __restrict__ scat_idx,
               const float* __restrict__ aIn,
               const __half* __restrict__ hIn,
               const float* __restrict__ bias,
               const __half* __restrict__ h0,
               __half* __restrict__ hOut,
               float* __restrict__ scatterOut,
               int M) {
    extern __shared__ char smem[];
    const uint32_t smem_u = smem_to_u32(smem);
    const int tid = threadIdx.x;
    const int bm = blockIdx.x * 64;
    int* s_row = (int*)(smem + SMEM_SROW);

    if (MODE != MODE_E2N) {
        if (tid < 64) s_row[tid] = rowIdx[bm + tid];
    }
    __syncthreads();

    const int lane = tid & 31;
    const int wid  = tid >> 5;
    const int wm   = wid / 10;    // 0..1
    const int wn   = wid % 10;    // 0..9

    // staging coords: threads 0..511 handle row r, 4 k-elems starting at q*4
    const int r = tid >> 3;       // 0..63 (tid<512)
    const int q = tid & 7;        // 0..7
    const int m_st = bm + r;
    const bool stager = (tid < 512);

    float acc[32];
    #pragma unroll
    for (int i = 0; i < 32; i++) acc[i] = 0.f;

    auto loadA = [&](int c) -> Pref {
        Pref pf;
        pf.a0 = make_float4(0.f, 0.f, 0.f, 0.f);
        pf.h0v = make_uint2(0u, 0u);
        if (!stager) return pf;
        const int ka = c * KCHUNK + q * 4;
        if (MODE == MODE_CONV) {
            if (ka + 4 <= K) {
                pf.a0  = *(const float4*)(aIn + (size_t)s_row[r] * HID + ka);
                pf.h0v = *(const uint2*)(hIn + (size_t)(bm + (r ^ 1)) * HID + ka);
            }
        } else if (MODE == MODE_INIT) {
            if (ka + 4 <= F_NODE)
                pf.a0 = *(const float4*)(x + (size_t)s_row[r] * F_NODE + ka);
            else if (ka >= F_NODE && ka + 4 <= F_NODE + F_EDGE)
                pf.a0 = *(const float4*)(edge_attr + (size_t)m_st * F_EDGE + (ka - F_NODE));
        } else { // E2N
            if (m_st < M) {
                if (ka + 4 <= F_NODE)
                    pf.a0 = *(const float4*)(x + (size_t)m_st * F_NODE + ka);
                else if (ka >= F_NODE && ka - F_NODE + 4 <= HID)
                    pf.a0 = *(const float4*)(aIn + (size_t)m_st * HID + (ka - F_NODE));
            }
        }
        return pf;
    };

    auto storeA = [&](int buf, const Pref& pf) {
        if (!stager) return;
        uint2 h;
        if (MODE == MODE_CONV) {
            float2 h0a = unpack_h2(pf.h0v.x), h0b = unpack_h2(pf.h0v.y);
            h.x = pack_h2(pf.a0.x - h0a.x, pf.a0.y - h0a.y);
            h.y = pack_h2(pf.a0.z - h0b.x, pf.a0.w - h0b.y);
        } else {
            h.x = pack_h2(pf.a0.x, pf.a0.y);
            h.y = pack_h2(pf.a0.z, pf.a0.w);
        }
        const uint32_t off = swzoff((uint32_t)r, (uint32_t)(q >> 1)) + (uint32_t)((q & 1) * 8);
        *(uint2*)(smem + SMEM_A_OFF + buf * 4096 + off) = h;
    };

    auto issueB = [&](int c, int buf) {
        const unsigned char* src = g_W + (size_t)(WBASE + c) * WCHUNK_BYTES;
        uint32_t dst = smem_u + SMEM_B_OFF + buf * WCHUNK_BYTES;
        CP_ASYNC16(dst + tid * 16, src + tid * 16);
        CP_ASYNC16(dst + (tid + NTHREADS) * 16, src + (tid + NTHREADS) * 16);
    };

    auto mmaChunk = [&](int buf) {
        const uint32_t At = smem_u + SMEM_A_OFF + buf * 4096;
        const uint32_t Bt = smem_u + SMEM_B_OFF + buf * WCHUNK_BYTES;
        #pragma unroll
        for (int ks = 0; ks < 2; ks++) {
            uint32_t af[2][4];
            const uint32_t agrp = (uint32_t)(ks * 2 + (lane >> 4));
            #pragma unroll
            for (int mt = 0; mt < 2; mt++) {
                const uint32_t row = (uint32_t)(wm * 32 + mt * 16 + (lane & 15));
                LDSM_X4(af[mt], At + swzoff(row, agrp));
            }
            #pragma unroll
            for (int pg = 0; pg < 2; pg++) {
                const uint32_t nrow = (uint32_t)(wn * 32 + pg * 16 + ((lane >> 4) << 3) + (lane & 7));
                const uint32_t bgrp = (uint32_t)(ks * 2 + ((lane >> 3) & 1));
                uint32_t bf[4];
                LDSM_X4(bf, Bt + swzoff(nrow, bgrp));
                #pragma unroll
                for (int mt = 0; mt < 2; mt++)
                    #pragma unroll
                    for (int nt = 0; nt < 2; nt++)
                        MMA_F16(&acc[((mt * 2 + pg) * 2 + nt) * 4], af[mt], &bf[nt * 2]);
            }
        }
    };

    // prologue: stage chunk 0
    {
        Pref p0 = loadA(0);
        issueB(0, 0);
        storeA(0, p0);
        CP_COMMIT();
        CP_WAIT0();
    }
    __syncthreads();

    for (int c = 0; c < C; c++) {
        const int buf = c & 1;
        Pref pn;
        const bool more = (c + 1 < C);
        if (more) {
            pn = loadA(c + 1);
            issueB(c + 1, buf ^ 1);
            CP_COMMIT();
        }
        mmaChunk(buf);
        if (more) {
            storeA(buf ^ 1, pn);
            CP_WAIT0();
            __syncthreads();
        }
    }

    // ---- epilogue: bias + skip + relu, fp16 h write, fp32 scatter-add ----
    #pragma unroll
    for (int mt = 0; mt < 2; mt++) {
        #pragma unroll
        for (int rh = 0; rh < 2; rh++) {
            const int m = bm + wm * 32 + mt * 16 + (lane >> 2) + rh * 8;
            if (m >= M) continue;
            const int sc = scat_idx[m];
            const __half* h0r = h0 + (size_t)m * HID;
            __half* hor = hOut + (size_t)m * HID;
            float* scr = scatterOut + (size_t)sc * HID;
            #pragma unroll
            for (int pg = 0; pg < 2; pg++) {
                const int n = wn * 32 + pg * 16 + (lane & 3) * 4;
                if (n >= HID) continue;
                const float* d0 = &acc[((mt * 2 + pg) * 2 + 0) * 4];
                const float* d1 = &acc[((mt * 2 + pg) * 2 + 1) * 4];
                float4 v;
                v.x = d0[rh * 2 + 0]; v.y = d0[rh * 2 + 1];
                v.z = d1[rh * 2 + 0]; v.w = d1[rh * 2 + 1];
                const float4 bb = __ldg((const float4*)(bias + n));
                v.x += bb.x; v.y += bb.y; v.z += bb.z; v.w += bb.w;
                if (MODE == MODE_CONV) {
                    const uint2 sr = *(const uint2*)(h0r + n);
                    float2 s0 = unpack_h2(sr.x), s1 = unpack_h2(sr.y);
                    v.x += s0.x; v.y += s0.y; v.z += s1.x; v.w += s1.y;
                }
                v.x = fmaxf(v.x, 0.f); v.y = fmaxf(v.y, 0.f);
                v.z = fmaxf(v.z, 0.f); v.w = fmaxf(v.w, 0.f);
                if (WRITE_H) {
                    uint2 hw;
                    hw.x = pack_h2(v.x, v.y);
                    hw.y = pack_h2(v.z, v.w);
                    *(uint2*)(hor + n) = hw;
                }
                asm volatile("red.global.add.v4.f32 [%0], {%1, %2, %3, %4};"
                             :: "l"(scr + n), "f"(v.x), "f"(v.y), "f"(v.z), "f"(v.w)
                             : "memory");
            }
        }
    }
}

__global__ void zero_kernel(float4* __restrict__ p, int n4) {
    int i = blockIdx.x * blockDim.x + threadIdx.x;
    if (i < n4) p[i] = make_float4(0.f, 0.f, 0.f, 0.f);
}

__global__ void ffn_kernel(const float* __restrict__ pooled,
                           const float* __restrict__ W,
                           const float* __restrict__ b,
                           float* __restrict__ out) {
    int g = blockIdx.x;
    int lane = threadIdx.x;
    float s = 0.f;
    for (int k = lane; k < HID; k += 32)
        s += pooled[g * HID + k] * W[k];
    #pragma unroll
    for (int o = 16; o > 0; o >>= 1)
        s += __shfl_xor_sync(0xFFFFFFFFu, s, o);
    if (lane == 0) out[g] = s + b[0];
}

extern "C" void kernel_launch(void* const* d_in, const int* in_sizes, int n_in,
                              void* d_out, int out_size) {
    const float* x         = (const float*)d_in[0];
    const float* edge_attr = (const float*)d_in[1];
    const int*   edge_idx  = (const int*)  d_in[2];
    const int*   batch     = (const int*)  d_in[3];
    const float* W_init    = (const float*)d_in[4];
    const float* b_init    = (const float*)d_in[5];
    const float* W_convs   = (const float*)d_in[6];
    const float* b_convs   = (const float*)d_in[7];
    const float* W_e2n     = (const float*)d_in[8];
    const float* b_e2n     = (const float*)d_in[9];
    const float* W_ffn     = (const float*)d_in[10];
    const float* b_ffn     = (const float*)d_in[11];
    float* out = (float*)d_out;

    const int* row = edge_idx;
    const int* col = edge_idx + N_EDGES;

    __half *h0, *hA, *hB;
    float *aA, *aB, *pooled;
    cudaGetSymbolAddress((void**)&h0, g_h0);
    cudaGetSymbolAddress((void**)&hA, g_hA);
    cudaGetSymbolAddress((void**)&hB, g_hB);
    cudaGetSymbolAddress((void**)&aA, g_aA);
    cudaGetSymbolAddress((void**)&aB, g_aB);
    cudaGetSymbolAddress((void**)&pooled, g_pooled);

    cudaFuncSetAttribute(fused_mma<MODE_INIT, F_NODE + F_EDGE, 3, 0, true>,
                         cudaFuncAttributeMaxDynamicSharedMemorySize, SMEM_TOTAL);
    cudaFuncSetAttribute(fused_mma<MODE_CONV, HID, 10, 3, true>,
                         cudaFuncAttributeMaxDynamicSharedMemorySize, SMEM_TOTAL);
    cudaFuncSetAttribute(fused_mma<MODE_CONV, HID, 10, 13, true>,
                         cudaFuncAttributeMaxDynamicSharedMemorySize, SMEM_TOTAL);
    cudaFuncSetAttribute(fused_mma<MODE_CONV, HID, 10, 23, false>,
                         cudaFuncAttributeMaxDynamicSharedMemorySize, SMEM_TOTAL);
    cudaFuncSetAttribute(fused_mma<MODE_E2N, F_NODE + HID, 12, 33, false>,
                         cudaFuncAttributeMaxDynamicSharedMemorySize, SMEM_TOTAL);

    const int NA = N_NODES * HID;
    const int gE = N_EDGES / 64;               // 5000
    const int gN = (N_NODES + 63) / 64;        // 313

    // weight preprocessing (fp16 + transpose + permute + swizzle)
    prep_weights<<<(TOTAL_WCHUNKS * WCHUNK_ELEMS + 255) / 256, 256>>>(W_init, W_convs, W_e2n);

    // init: h0 = relu(cat(x[row], edge_attr) @ W_init + b); scatter -> aA
    zero_kernel<<<(NA / 4 + 255) / 256, 256>>>((float4*)aA, NA / 4);
    fused_mma<MODE_INIT, F_NODE + F_EDGE, 3, 0, true><<<gE, NTHREADS, SMEM_TOTAL>>>(
        x, edge_attr, row, col, nullptr, nullptr, b_init, h0, h0, aA, N_EDGES);

    // conv0: A = aA[row] - rev(h0); h = relu(A@W0 + b0 + h0); scatter -> aB
    zero_kernel<<<(NA / 4 + 255) / 256, 256>>>((float4*)aB, NA / 4);
    fused_mma<MODE_CONV, HID, 10, 3, true><<<gE, NTHREADS, SMEM_TOTAL>>>(
        nullptr, nullptr, row, col, aA, h0, b_convs + 0 * HID, h0, hA, aB, N_EDGES);

    // conv1
    zero_kernel<<<(NA / 4 + 255) / 256, 256>>>((float4*)aA, NA / 4);
    fused_mma<MODE_CONV, HID, 10, 13, true><<<gE, NTHREADS, SMEM_TOTAL>>>(
        nullptr, nullptr, row, col, aB, hA, b_convs + 1 * HID, h0, hB, aA, N_EDGES);

    // conv2: scatter only -> aB (= s); h not written
    zero_kernel<<<(NA / 4 + 255) / 256, 256>>>((float4*)aB, NA / 4);
    fused_mma<MODE_CONV, HID, 10, 23, false><<<gE, NTHREADS, SMEM_TOTAL>>>(
        nullptr, nullptr, row, col, aA, hB, b_convs + 2 * HID, h0, hA, aB, N_EDGES);

    // e2n: hn = relu(cat(x, s) @ W_e2n + b); scatter by batch -> pooled
    zero_kernel<<<(N_GRAPHS * HID / 4 + 255) / 256, 256>>>((float4*)pooled, N_GRAPHS * HID / 4);
    fused_mma<MODE_E2N, F_NODE + HID, 12, 33, false><<<gN, NTHREADS, SMEM_TOTAL>>>(
        x, nullptr, nullptr, batch, aB, nullptr, b_e2n, h0, hA, pooled, N_NODES);

    // out = pooled @ W_ffn + b
    ffn_kernel<<<N_GRAPHS, 32>>>(pooled, W_ffn, b_ffn, out);
}